// round 1
// baseline (speedup 1.0000x reference)
#include <cuda_runtime.h>
#include <math.h>

#define BI   256
#define BC   256
#define LREG 36
#define TMAX 64
#define DD   1024
#define DR   256
#define NK   3
#define EPSF 1e-8f

#define SPLITK 4

// ---------------- scratch (device globals; no allocation allowed) -------------
__device__ float g_sab[3 * BI * DD];          // rows: s[0..255], a[256..511], b[512..767]
__device__ float g_xqr[3 * BI * DD];          // X, Q, R (post conv)
__device__ float g_capv[BC * DD];             // normalized caption vectors
__device__ float g_G[NK * DD];                // folded proj_w @ red_w
__device__ float g_pb2[NK];                   // folded logit bias
__device__ float g_w0[BC];
__device__ float g_w2[BC];
__device__ float g_Dm[SPLITK * 3 * BI * BC];  // split-K Gram partials (deterministic sum later)
__device__ float g_scal[BI * 8];              // XX,QQ,RR,XQ,XR,QR per image

// ---------------- fold: G = proj_w @ red_w, pb2 = proj_w @ red_b + proj_b ------
__global__ void k_fold(const float* __restrict__ red_w, const float* __restrict__ red_b,
                       const float* __restrict__ proj_w, const float* __restrict__ proj_b) {
    int k = blockIdx.y;
    int d = blockIdx.x * 256 + threadIdx.x;
    float acc = 0.f;
#pragma unroll 4
    for (int e = 0; e < DR; e++) acc += proj_w[k * DR + e] * red_w[e * DD + d];
    g_G[k * DD + d] = acc;

    if (blockIdx.x == 0) {
        __shared__ float sm[256];
        sm[threadIdx.x] = proj_w[k * DR + threadIdx.x] * red_b[threadIdx.x];
        __syncthreads();
        for (int s = 128; s > 0; s >>= 1) {
            if (threadIdx.x < s) sm[threadIdx.x] += sm[threadIdx.x + s];
            __syncthreads();
        }
        if (threadIdx.x == 0) g_pb2[k] = sm[0] + proj_b[k];
    }
}

// ---------------- image reduce: s = sum/L, a = last/L, b = first/L -------------
__global__ void k_img(const float* __restrict__ img) {
    int i = blockIdx.x;
    int c = blockIdx.y * 128 + threadIdx.x;   // float4 column, 0..255
    const float4* p = ((const float4*)img) + (size_t)i * (LREG * DD / 4) + c;
    float4 first = p[0];
    float4 s = first;
    float4 last = first;
#pragma unroll
    for (int l = 1; l < LREG; l++) {
        float4 v = p[l * (DD / 4)];
        s.x += v.x; s.y += v.y; s.z += v.z; s.w += v.w;
        if (l == LREG - 1) last = v;
    }
    const float inv = 1.f / (float)LREG;
    float4* out = (float4*)g_sab;
    float4 sv = make_float4(s.x * inv, s.y * inv, s.z * inv, s.w * inv);
    float4 av = make_float4(last.x * inv, last.y * inv, last.z * inv, last.w * inv);
    float4 bv = make_float4(first.x * inv, first.y * inv, first.z * inv, first.w * inv);
    out[(size_t)i * (DD / 4) + c] = sv;
    out[(size_t)(BI + i) * (DD / 4) + c] = av;
    out[(size_t)(2 * BI + i) * (DD / 4) + c] = bv;
}

// ---------------- caption: masked mean, l2norm, folded softmax weights ---------
__global__ void k_cap(const float* __restrict__ cap, const int* __restrict__ lens) {
    int b = blockIdx.x;
    int c = threadIdx.x;                      // float4 column
    int len = lens[b];
    const float4* p = ((const float4*)cap) + (size_t)b * (TMAX * DD / 4) + c;
    float4 acc = make_float4(0.f, 0.f, 0.f, 0.f);
    for (int t = 0; t < len; t++) {
        float4 v = p[t * (DD / 4)];
        acc.x += v.x; acc.y += v.y; acc.z += v.z; acc.w += v.w;
    }
    float inv = 1.f / (float)len;
    float4 f = make_float4(acc.x * inv, acc.y * inv, acc.z * inv, acc.w * inv);

    float n2 = f.x * f.x + f.y * f.y + f.z * f.z + f.w * f.w;
    const float4* G4 = (const float4*)g_G;
    float4 g0 = G4[0 * (DD / 4) + c];
    float4 g1 = G4[1 * (DD / 4) + c];
    float4 g2 = G4[2 * (DD / 4) + c];
    float d0 = f.x * g0.x + f.y * g0.y + f.z * g0.z + f.w * g0.w;
    float d1 = f.x * g1.x + f.y * g1.y + f.z * g1.z + f.w * g1.w;
    float d2 = f.x * g2.x + f.y * g2.y + f.z * g2.z + f.w * g2.w;

#pragma unroll
    for (int o = 16; o > 0; o >>= 1) {
        n2 += __shfl_xor_sync(0xffffffffu, n2, o);
        d0 += __shfl_xor_sync(0xffffffffu, d0, o);
        d1 += __shfl_xor_sync(0xffffffffu, d1, o);
        d2 += __shfl_xor_sync(0xffffffffu, d2, o);
    }
    __shared__ float red[4][8];
    __shared__ float s_invn;
    int wrp = threadIdx.x >> 5, ln = threadIdx.x & 31;
    if (ln == 0) { red[0][wrp] = n2; red[1][wrp] = d0; red[2][wrp] = d1; red[3][wrp] = d2; }
    __syncthreads();
    if (threadIdx.x == 0) {
        float N2 = 0, D0 = 0, D1 = 0, D2 = 0;
#pragma unroll
        for (int j = 0; j < 8; j++) { N2 += red[0][j]; D0 += red[1][j]; D1 += red[2][j]; D2 += red[3][j]; }
        s_invn = 1.f / (sqrtf(N2) + EPSF);
        float l0 = D0 + g_pb2[0], l1 = D1 + g_pb2[1], l2 = D2 + g_pb2[2];
        float mx = fmaxf(l0, fmaxf(l1, l2));
        float e0 = expf(l0 - mx), e1 = expf(l1 - mx), e2 = expf(l2 - mx);
        float is = 1.f / (e0 + e1 + e2);
        g_w0[b] = e0 * is;
        g_w2[b] = e2 * is;
    }
    __syncthreads();
    float invn = s_invn;
    float4 cv = make_float4(f.x * invn, f.y * invn, f.z * invn, f.w * invn);
    ((float4*)g_capv)[(size_t)b * (DD / 4) + c] = cv;
}

// ---------------- generic TN GEMM: C[m,n] = sum_k A[m,k]*B[n,k] ----------------
// 64x64 tile, 256 threads, 4x4 micro-tile, K-chunk 16. splitK via blockIdx.z
// writing to disjoint C slices (deterministic).
#define BM 64
#define BN 64
#define BK 16
#define SSTR 72  // smem row stride in floats (64 + 8 pad)

__global__ void __launch_bounds__(256) k_gemm(
    const float* __restrict__ A, const float* __restrict__ B, float* __restrict__ C,
    int N, int K, int kChunk, const float* __restrict__ bias, int biasRowLim) {
    __shared__ __align__(16) float As[BK * SSTR];
    __shared__ __align__(16) float Bs[BK * SSTR];

    int m0 = blockIdx.y * BM;
    int n0 = blockIdx.x * BN;
    int kBeg = blockIdx.z * kChunk;
    int kEnd = kBeg + kChunk;
    int t = threadIdx.x;
    int tx = t & 15, ty = t >> 4;
    int lrow = t >> 2;
    int lk = (t & 3) * 4;

    float acc[4][4] = {};
    for (int kc = kBeg; kc < kEnd; kc += BK) {
        float4 va = *(const float4*)&A[(size_t)(m0 + lrow) * K + kc + lk];
        float4 vb = *(const float4*)&B[(size_t)(n0 + lrow) * K + kc + lk];
        As[(lk + 0) * SSTR + lrow] = va.x;
        As[(lk + 1) * SSTR + lrow] = va.y;
        As[(lk + 2) * SSTR + lrow] = va.z;
        As[(lk + 3) * SSTR + lrow] = va.w;
        Bs[(lk + 0) * SSTR + lrow] = vb.x;
        Bs[(lk + 1) * SSTR + lrow] = vb.y;
        Bs[(lk + 2) * SSTR + lrow] = vb.z;
        Bs[(lk + 3) * SSTR + lrow] = vb.w;
        __syncthreads();
#pragma unroll
        for (int kk = 0; kk < BK; kk++) {
            float4 a = *(const float4*)&As[kk * SSTR + ty * 4];
            float4 bb = *(const float4*)&Bs[kk * SSTR + tx * 4];
            acc[0][0] += a.x * bb.x; acc[0][1] += a.x * bb.y; acc[0][2] += a.x * bb.z; acc[0][3] += a.x * bb.w;
            acc[1][0] += a.y * bb.x; acc[1][1] += a.y * bb.y; acc[1][2] += a.y * bb.z; acc[1][3] += a.y * bb.w;
            acc[2][0] += a.z * bb.x; acc[2][1] += a.z * bb.y; acc[2][2] += a.z * bb.z; acc[2][3] += a.z * bb.w;
            acc[3][0] += a.w * bb.x; acc[3][1] += a.w * bb.y; acc[3][2] += a.w * bb.z; acc[3][3] += a.w * bb.w;
        }
        __syncthreads();
    }
    // epilogue: write to this z-slice of C
    float* Cz = C + (size_t)blockIdx.z * (3 * BI) * N;
#pragma unroll
    for (int i = 0; i < 4; i++) {
        int m = m0 + ty * 4 + i;
        bool addb = (bias != nullptr) && (blockIdx.z == 0) && (m < biasRowLim);
#pragma unroll
        for (int j = 0; j < 4; j++) {
            int n = n0 + tx * 4 + j;
            float v = acc[i][j];
            if (addb) v += bias[n];
            Cz[(size_t)m * N + n] = v;
        }
    }
}

// ---------------- per-image Gram scalars among X,Q,R ---------------------------
__global__ void k_scal() {
    int i = blockIdx.x;
    int c = threadIdx.x;
    const float4* X = ((const float4*)g_xqr) + (size_t)i * (DD / 4);
    const float4* Q = ((const float4*)g_xqr) + (size_t)(BI + i) * (DD / 4);
    const float4* R = ((const float4*)g_xqr) + (size_t)(2 * BI + i) * (DD / 4);
    float4 x = X[c], q = Q[c], r = R[c];
    float v[6];
    v[0] = x.x * x.x + x.y * x.y + x.z * x.z + x.w * x.w;
    v[1] = q.x * q.x + q.y * q.y + q.z * q.z + q.w * q.w;
    v[2] = r.x * r.x + r.y * r.y + r.z * r.z + r.w * r.w;
    v[3] = x.x * q.x + x.y * q.y + x.z * q.z + x.w * q.w;
    v[4] = x.x * r.x + x.y * r.y + x.z * r.z + x.w * r.w;
    v[5] = x.x * r.x * 0.f; // placeholder replaced below
    v[5] = q.x * r.x + q.y * r.y + q.z * r.z + q.w * r.w;
#pragma unroll
    for (int o = 16; o > 0; o >>= 1)
#pragma unroll
        for (int j = 0; j < 6; j++) v[j] += __shfl_xor_sync(0xffffffffu, v[j], o);
    __shared__ float red[6][8];
    int wrp = threadIdx.x >> 5, ln = threadIdx.x & 31;
    if (ln == 0)
#pragma unroll
        for (int j = 0; j < 6; j++) red[j][wrp] = v[j];
    __syncthreads();
    if (threadIdx.x < 6) {
        float s = 0.f;
#pragma unroll
        for (int j = 0; j < 8; j++) s += red[threadIdx.x][j];
        g_scal[i * 8 + threadIdx.x] = s;
    }
}

// ---------------- final combine -----------------------------------------------
__global__ void k_final(float* __restrict__ out) {
    int i = blockIdx.x;
    int b = threadIdx.x;
    float XX = g_scal[i * 8 + 0], QQ = g_scal[i * 8 + 1], RR = g_scal[i * 8 + 2];
    float XQ = g_scal[i * 8 + 3], XR = g_scal[i * 8 + 4], QR = g_scal[i * 8 + 5];
    float w0 = g_w0[b], w2 = g_w2[b];
    float DX = 0.f, DQ = 0.f, DRv = 0.f;
#pragma unroll
    for (int z = 0; z < SPLITK; z++) {
        const float* Dz = g_Dm + (size_t)z * (3 * BI) * BC;
        DX += Dz[(size_t)i * BC + b];
        DQ += Dz[(size_t)(BI + i) * BC + b];
        DRv += Dz[(size_t)(2 * BI + i) * BC + b];
    }
    float numer = DX - w0 * DQ - w2 * DRv;
    float n2 = XX + w0 * w0 * QQ + w2 * w2 * RR - 2.f * (w0 * XQ + w2 * XR - w0 * w2 * QR);
    n2 = fmaxf(n2, 0.f);
    out[(size_t)i * BC + b] = numer / (sqrtf(n2) + EPSF);
}

// ---------------- launcher -----------------------------------------------------
extern "C" void kernel_launch(void* const* d_in, const int* in_sizes, int n_in,
                              void* d_out, int out_size) {
    const float* img    = (const float*)d_in[0];
    const float* cap    = (const float*)d_in[1];
    const int*   lens   = (const int*)d_in[2];
    const float* red_w  = (const float*)d_in[3];
    const float* red_b  = (const float*)d_in[4];
    const float* proj_w = (const float*)d_in[5];
    const float* proj_b = (const float*)d_in[6];
    const float* conv_w = (const float*)d_in[7];
    const float* conv_b = (const float*)d_in[8];
    float* out = (float*)d_out;

    float *sab, *xqr, *capv, *Dm;
    cudaGetSymbolAddress((void**)&sab, g_sab);
    cudaGetSymbolAddress((void**)&xqr, g_xqr);
    cudaGetSymbolAddress((void**)&capv, g_capv);
    cudaGetSymbolAddress((void**)&Dm, g_Dm);

    k_fold<<<dim3(DD / 256, NK), 256>>>(red_w, red_b, proj_w, proj_b);
    k_img<<<dim3(BI, 2), 128>>>(img);
    k_cap<<<BC, 256>>>(cap, lens);

    // conv GEMM: [s;a;b](768,1024) @ conv_w^T(1024,1024) -> XQR (bias on X rows)
    k_gemm<<<dim3(DD / BN, (3 * BI) / BM, 1), 256>>>(sab, conv_w, xqr, DD, DD, DD, conv_b, BI);

    // Gram GEMM: [X;Q;R](768,1024) @ cap_v^T(256,1024) -> Dm, split-K into 4 slices
    k_gemm<<<dim3(BC / BN, (3 * BI) / BM, SPLITK), 256>>>(xqr, capv, Dm, BC, DD, DD / SPLITK, nullptr, 0);

    k_scal<<<BI, 256>>>();
    k_final<<<BI, 256>>>(out);
}

// round 2
// speedup vs baseline: 1.1590x; 1.1590x over previous
#include <cuda_runtime.h>
#include <math.h>

#define BI   256
#define BC   256
#define LREG 36
#define TMAX 64
#define DD   1024
#define DR   256
#define NK   3
#define EPSF 1e-8f

#define SPLITK_C 4   // conv GEMM split-K
#define SPLITK_G 8   // Gram GEMM split-K

// ---------------- scratch (device globals; no allocation allowed) -------------
__device__ float g_sab[3 * BI * DD];               // rows: s, a, b
__device__ float g_xqrp[SPLITK_C * 3 * BI * DD];   // conv GEMM split-K partials
__device__ float g_xqr[3 * BI * DD];               // X, Q, R (post conv, reduced)
__device__ float g_capv[BC * DD];                  // normalized caption vectors
__device__ float g_G[NK * DD];                     // folded proj_w @ red_w
__device__ float g_pb2[NK];                        // folded logit bias
__device__ float g_w0[BC];
__device__ float g_w2[BC];
__device__ float g_Dm[SPLITK_G * 3 * BI * BC];     // Gram split-K partials
__device__ float g_scal[BI * 8];                   // XX,QQ,RR,XQ,XR,QR per image

// ---------------- fold: G = proj_w @ red_w, pb2 = proj_w @ red_b + proj_b ------
__global__ void k_fold(const float* __restrict__ red_w, const float* __restrict__ red_b,
                       const float* __restrict__ proj_w, const float* __restrict__ proj_b) {
    int k = blockIdx.y;
    int d = blockIdx.x * 256 + threadIdx.x;
    float acc = 0.f;
#pragma unroll 4
    for (int e = 0; e < DR; e++) acc += proj_w[k * DR + e] * red_w[e * DD + d];
    g_G[k * DD + d] = acc;

    if (blockIdx.x == 0) {
        __shared__ float sm[256];
        sm[threadIdx.x] = proj_w[k * DR + threadIdx.x] * red_b[threadIdx.x];
        __syncthreads();
        for (int s = 128; s > 0; s >>= 1) {
            if (threadIdx.x < s) sm[threadIdx.x] += sm[threadIdx.x + s];
            __syncthreads();
        }
        if (threadIdx.x == 0) g_pb2[k] = sm[0] + proj_b[k];
    }
}

// ---------------- image reduce: s = sum/L, a = last/L, b = first/L -------------
__global__ void k_img(const float* __restrict__ img) {
    int i = blockIdx.x;
    int c = blockIdx.y * 128 + threadIdx.x;   // float4 column, 0..255
    const float4* p = ((const float4*)img) + (size_t)i * (LREG * DD / 4) + c;
    float4 first = p[0];
    float4 s = first;
    float4 last = first;
#pragma unroll
    for (int l = 1; l < LREG; l++) {
        float4 v = p[l * (DD / 4)];
        s.x += v.x; s.y += v.y; s.z += v.z; s.w += v.w;
        if (l == LREG - 1) last = v;
    }
    const float inv = 1.f / (float)LREG;
    float4* out = (float4*)g_sab;
    float4 sv = make_float4(s.x * inv, s.y * inv, s.z * inv, s.w * inv);
    float4 av = make_float4(last.x * inv, last.y * inv, last.z * inv, last.w * inv);
    float4 bv = make_float4(first.x * inv, first.y * inv, first.z * inv, first.w * inv);
    out[(size_t)i * (DD / 4) + c] = sv;
    out[(size_t)(BI + i) * (DD / 4) + c] = av;
    out[(size_t)(2 * BI + i) * (DD / 4) + c] = bv;
}

// ---------------- caption: masked mean, l2norm, folded softmax weights ---------
__global__ void k_cap(const float* __restrict__ cap, const int* __restrict__ lens) {
    int b = blockIdx.x;
    int c = threadIdx.x;                      // float4 column
    int len = lens[b];
    const float4* p = ((const float4*)cap) + (size_t)b * (TMAX * DD / 4) + c;
    float4 acc = make_float4(0.f, 0.f, 0.f, 0.f);
    for (int t = 0; t < len; t++) {
        float4 v = p[t * (DD / 4)];
        acc.x += v.x; acc.y += v.y; acc.z += v.z; acc.w += v.w;
    }
    float inv = 1.f / (float)len;
    float4 f = make_float4(acc.x * inv, acc.y * inv, acc.z * inv, acc.w * inv);

    float n2 = f.x * f.x + f.y * f.y + f.z * f.z + f.w * f.w;
    const float4* G4 = (const float4*)g_G;
    float4 g0 = G4[0 * (DD / 4) + c];
    float4 g1 = G4[1 * (DD / 4) + c];
    float4 g2 = G4[2 * (DD / 4) + c];
    float d0 = f.x * g0.x + f.y * g0.y + f.z * g0.z + f.w * g0.w;
    float d1 = f.x * g1.x + f.y * g1.y + f.z * g1.z + f.w * g1.w;
    float d2 = f.x * g2.x + f.y * g2.y + f.z * g2.z + f.w * g2.w;

#pragma unroll
    for (int o = 16; o > 0; o >>= 1) {
        n2 += __shfl_xor_sync(0xffffffffu, n2, o);
        d0 += __shfl_xor_sync(0xffffffffu, d0, o);
        d1 += __shfl_xor_sync(0xffffffffu, d1, o);
        d2 += __shfl_xor_sync(0xffffffffu, d2, o);
    }
    __shared__ float red[4][8];
    __shared__ float s_invn;
    int wrp = threadIdx.x >> 5, ln = threadIdx.x & 31;
    if (ln == 0) { red[0][wrp] = n2; red[1][wrp] = d0; red[2][wrp] = d1; red[3][wrp] = d2; }
    __syncthreads();
    if (threadIdx.x == 0) {
        float N2 = 0, D0 = 0, D1 = 0, D2 = 0;
#pragma unroll
        for (int j = 0; j < 8; j++) { N2 += red[0][j]; D0 += red[1][j]; D1 += red[2][j]; D2 += red[3][j]; }
        s_invn = 1.f / (sqrtf(N2) + EPSF);
        float l0 = D0 + g_pb2[0], l1 = D1 + g_pb2[1], l2 = D2 + g_pb2[2];
        float mx = fmaxf(l0, fmaxf(l1, l2));
        float e0 = expf(l0 - mx), e1 = expf(l1 - mx), e2 = expf(l2 - mx);
        float is = 1.f / (e0 + e1 + e2);
        g_w0[b] = e0 * is;
        g_w2[b] = e2 * is;
    }
    __syncthreads();
    float invn = s_invn;
    float4 cv = make_float4(f.x * invn, f.y * invn, f.z * invn, f.w * invn);
    ((float4*)g_capv)[(size_t)b * (DD / 4) + c] = cv;
}

// ---------------- generic TN GEMM: C[m,n] = sum_k A[m,k]*B[n,k] ----------------
// 64x64 tile, 256 threads, 4x4 micro-tile, K-chunk 16, register double-buffered
// global loads. splitK via blockIdx.z writing to disjoint C slices.
#define BM 64
#define BN 64
#define BK 16
#define SSTR 72  // smem row stride in floats (64 + 8 pad)

__global__ void __launch_bounds__(256) k_gemm(
    const float* __restrict__ A, const float* __restrict__ B, float* __restrict__ C,
    int N, int K, int kChunk) {
    __shared__ __align__(16) float As[BK * SSTR];
    __shared__ __align__(16) float Bs[BK * SSTR];

    int m0 = blockIdx.y * BM;
    int n0 = blockIdx.x * BN;
    int kBeg = blockIdx.z * kChunk;
    int kEnd = kBeg + kChunk;
    int t = threadIdx.x;
    int tx = t & 15, ty = t >> 4;
    int lrow = t >> 2;
    int lk = (t & 3) * 4;

    const float* Ap = &A[(size_t)(m0 + lrow) * K + lk];
    const float* Bp = &B[(size_t)(n0 + lrow) * K + lk];

    float acc[4][4] = {};
    // prefetch first tile into registers
    float4 va = *(const float4*)&Ap[kBeg];
    float4 vb = *(const float4*)&Bp[kBeg];

    for (int kc = kBeg; kc < kEnd; kc += BK) {
        As[(lk + 0) * SSTR + lrow] = va.x;
        As[(lk + 1) * SSTR + lrow] = va.y;
        As[(lk + 2) * SSTR + lrow] = va.z;
        As[(lk + 3) * SSTR + lrow] = va.w;
        Bs[(lk + 0) * SSTR + lrow] = vb.x;
        Bs[(lk + 1) * SSTR + lrow] = vb.y;
        Bs[(lk + 2) * SSTR + lrow] = vb.z;
        Bs[(lk + 3) * SSTR + lrow] = vb.w;
        __syncthreads();
        if (kc + BK < kEnd) {
            va = *(const float4*)&Ap[kc + BK];
            vb = *(const float4*)&Bp[kc + BK];
        }
#pragma unroll
        for (int kk = 0; kk < BK; kk++) {
            float4 a = *(const float4*)&As[kk * SSTR + ty * 4];
            float4 bb = *(const float4*)&Bs[kk * SSTR + tx * 4];
            acc[0][0] += a.x * bb.x; acc[0][1] += a.x * bb.y; acc[0][2] += a.x * bb.z; acc[0][3] += a.x * bb.w;
            acc[1][0] += a.y * bb.x; acc[1][1] += a.y * bb.y; acc[1][2] += a.y * bb.z; acc[1][3] += a.y * bb.w;
            acc[2][0] += a.z * bb.x; acc[2][1] += a.z * bb.y; acc[2][2] += a.z * bb.z; acc[2][3] += a.z * bb.w;
            acc[3][0] += a.w * bb.x; acc[3][1] += a.w * bb.y; acc[3][2] += a.w * bb.z; acc[3][3] += a.w * bb.w;
        }
        __syncthreads();
    }
    // epilogue: write to this z-slice of C
    float* Cz = C + (size_t)blockIdx.z * (3 * BI) * N;
#pragma unroll
    for (int i = 0; i < 4; i++) {
        int m = m0 + ty * 4 + i;
#pragma unroll
        for (int j = 0; j < 4; j++) {
            int n = n0 + tx * 4 + j;
            Cz[(size_t)m * N + n] = acc[i][j];
        }
    }
}

// ---------------- reduce conv split-K slices + bias ----------------------------
__global__ void k_reduce(const float* __restrict__ bias) {
    int m = blockIdx.x;                       // 0..767
    int c = threadIdx.x;                      // float4 column, 0..255
    const float4* P = (const float4*)g_xqrp;
    size_t idx = (size_t)m * (DD / 4) + c;
    const size_t stride = (size_t)(3 * BI) * (DD / 4);
    float4 v0 = P[idx];
    float4 v1 = P[idx + stride];
    float4 v2 = P[idx + 2 * stride];
    float4 v3 = P[idx + 3 * stride];
    float4 r = make_float4(v0.x + v1.x + v2.x + v3.x,
                           v0.y + v1.y + v2.y + v3.y,
                           v0.z + v1.z + v2.z + v3.z,
                           v0.w + v1.w + v2.w + v3.w);
    if (m < BI) {
        float4 bb = ((const float4*)bias)[c];
        r.x += bb.x; r.y += bb.y; r.z += bb.z; r.w += bb.w;
    }
    ((float4*)g_xqr)[idx] = r;
}

// ---------------- per-image Gram scalars among X,Q,R ---------------------------
__global__ void k_scal() {
    int i = blockIdx.x;
    int c = threadIdx.x;
    const float4* X = ((const float4*)g_xqr) + (size_t)i * (DD / 4);
    const float4* Q = ((const float4*)g_xqr) + (size_t)(BI + i) * (DD / 4);
    const float4* R = ((const float4*)g_xqr) + (size_t)(2 * BI + i) * (DD / 4);
    float4 x = X[c], q = Q[c], r = R[c];
    float v[6];
    v[0] = x.x * x.x + x.y * x.y + x.z * x.z + x.w * x.w;
    v[1] = q.x * q.x + q.y * q.y + q.z * q.z + q.w * q.w;
    v[2] = r.x * r.x + r.y * r.y + r.z * r.z + r.w * r.w;
    v[3] = x.x * q.x + x.y * q.y + x.z * q.z + x.w * q.w;
    v[4] = x.x * r.x + x.y * r.y + x.z * r.z + x.w * r.w;
    v[5] = q.x * r.x + q.y * r.y + q.z * r.z + q.w * r.w;
#pragma unroll
    for (int o = 16; o > 0; o >>= 1)
#pragma unroll
        for (int j = 0; j < 6; j++) v[j] += __shfl_xor_sync(0xffffffffu, v[j], o);
    __shared__ float red[6][8];
    int wrp = threadIdx.x >> 5, ln = threadIdx.x & 31;
    if (ln == 0)
#pragma unroll
        for (int j = 0; j < 6; j++) red[j][wrp] = v[j];
    __syncthreads();
    if (threadIdx.x < 6) {
        float s = 0.f;
#pragma unroll
        for (int j = 0; j < 8; j++) s += red[threadIdx.x][j];
        g_scal[i * 8 + threadIdx.x] = s;
    }
}

// ---------------- final combine -----------------------------------------------
__global__ void k_final(float* __restrict__ out) {
    int i = blockIdx.x;
    int b = threadIdx.x;
    float XX = g_scal[i * 8 + 0], QQ = g_scal[i * 8 + 1], RR = g_scal[i * 8 + 2];
    float XQ = g_scal[i * 8 + 3], XR = g_scal[i * 8 + 4], QR = g_scal[i * 8 + 5];
    float w0 = g_w0[b], w2 = g_w2[b];
    float DX = 0.f, DQ = 0.f, DRv = 0.f;
#pragma unroll
    for (int z = 0; z < SPLITK_G; z++) {
        const float* Dz = g_Dm + (size_t)z * (3 * BI) * BC;
        DX += Dz[(size_t)i * BC + b];
        DQ += Dz[(size_t)(BI + i) * BC + b];
        DRv += Dz[(size_t)(2 * BI + i) * BC + b];
    }
    float numer = DX - w0 * DQ - w2 * DRv;
    float n2 = XX + w0 * w0 * QQ + w2 * w2 * RR - 2.f * (w0 * XQ + w2 * XR - w0 * w2 * QR);
    n2 = fmaxf(n2, 0.f);
    out[(size_t)i * BC + b] = numer / (sqrtf(n2) + EPSF);
}

// ---------------- launcher -----------------------------------------------------
extern "C" void kernel_launch(void* const* d_in, const int* in_sizes, int n_in,
                              void* d_out, int out_size) {
    const float* img    = (const float*)d_in[0];
    const float* cap    = (const float*)d_in[1];
    const int*   lens   = (const int*)d_in[2];
    const float* red_w  = (const float*)d_in[3];
    const float* red_b  = (const float*)d_in[4];
    const float* proj_w = (const float*)d_in[5];
    const float* proj_b = (const float*)d_in[6];
    const float* conv_w = (const float*)d_in[7];
    const float* conv_b = (const float*)d_in[8];
    float* out = (float*)d_out;

    float *sab, *xqrp, *xqr, *capv, *Dm;
    cudaGetSymbolAddress((void**)&sab, g_sab);
    cudaGetSymbolAddress((void**)&xqrp, g_xqrp);
    cudaGetSymbolAddress((void**)&xqr, g_xqr);
    cudaGetSymbolAddress((void**)&capv, g_capv);
    cudaGetSymbolAddress((void**)&Dm, g_Dm);

    k_fold<<<dim3(DD / 256, NK), 256>>>(red_w, red_b, proj_w, proj_b);
    k_img<<<dim3(BI, 2), 128>>>(img);
    k_cap<<<BC, 256>>>(cap, lens);

    // conv GEMM: [s;a;b](768,1024) @ conv_w^T(1024,1024) -> 4 K-slices
    k_gemm<<<dim3(DD / BN, (3 * BI) / BM, SPLITK_C), 256>>>(sab, conv_w, xqrp, DD, DD, DD / SPLITK_C);
    // sum slices + bias (bias only on X rows)
    k_reduce<<<3 * BI, 256>>>(conv_b);

    // Gram GEMM: [X;Q;R](768,1024) @ cap_v^T(256,1024) -> 8 K-slices
    k_gemm<<<dim3(BC / BN, (3 * BI) / BM, SPLITK_G), 256>>>(xqr, capv, Dm, BC, DD, DD / SPLITK_G);

    k_scal<<<BI, 256>>>();
    k_final<<<BI, 256>>>(out);
}